// round 10
// baseline (speedup 1.0000x reference)
#include <cuda_runtime.h>
#include <math_constants.h>

#define NPTS   8192
#define BATCH  4
#define KNN    4
#define QPB    224                 // queries (original indices) per block
#define THREADS 896                // 28 warps; 8 active query-lanes per warp
#define GRPX   37                  // 37*4 = 148 blocks = 1 full wave

#define NBINS  512
#define XMIN   (-6.0f)
#define BINW   (12.0f / NBINS)     // 0.0234375 within-bin jitter margin
#define INVW   (NBINS / 12.0f)
#define SLACK  1e-3f               // absorbs all fp32 rounding in the prune bound

// smem: pts_s[8192] float4 128K | idx_s[8192] int 32K | rank_of[8192] int 32K | cnt+tmp 4K
#define PTS_BYTES (NPTS * 16)
#define IDX_BYTES (NPTS * 4)
#define SMEM_BYTES (PTS_BYTES + 2 * IDX_BYTES + NBINS * 4 * 2)   // 200704 B

__device__ __forceinline__ int bin_of(float px) {
    // Contraction-proof: identical rounding at every call site.
    int bin = (int)__fmul_rn(__fsub_rn(px, XMIN), INVW);
    return min(max(bin, 0), NBINS - 1);
}

__device__ __forceinline__ bool better(float s, int oj, float v, int iv) {
    return (s > v) | ((s == v) & (oj < iv));
}

__global__ __launch_bounds__(THREADS, 1)
void knn_sorted_kernel(const float* __restrict__ x, float* __restrict__ out) {
    extern __shared__ char smem_raw[];
    float4* __restrict__ pts_s   = (float4*)smem_raw;
    int*    __restrict__ idx_s   = (int*)(smem_raw + PTS_BYTES);
    int*    __restrict__ rank_of = (int*)(smem_raw + PTS_BYTES + IDX_BYTES);
    int*    __restrict__ cnt     = (int*)(smem_raw + PTS_BYTES + 2 * IDX_BYTES);
    int*    __restrict__ tmp     = cnt + NBINS;

    const int b = blockIdx.y;
    const float* __restrict__ xb = x + (size_t)b * NPTS * 3;
    const int tid = threadIdx.x;

    // ---- 1) histogram over x-bins
    for (int i = tid; i < NBINS; i += THREADS) cnt[i] = 0;
    __syncthreads();
    for (int j = tid; j < NPTS; j += THREADS)
        atomicAdd(&cnt[bin_of(xb[3 * j])], 1);
    __syncthreads();

    // ---- 2) exclusive prefix (Kogge-Stone)
    if (tid < NBINS) tmp[tid] = cnt[tid];
    __syncthreads();
    for (int d = 1; d < NBINS; d <<= 1) {
        int v = 0;
        if (tid < NBINS && tid >= d) v = tmp[tid - d];
        __syncthreads();
        if (tid < NBINS) tmp[tid] += v;
        __syncthreads();
    }
    if (tid < NBINS) cnt[tid] = tmp[tid] - cnt[tid];   // exclusive offsets (cursor)
    __syncthreads();

    // ---- 3) scatter into bin-sorted order; record rank of each original index
    for (int j = tid; j < NPTS; j += THREADS) {
        float px = xb[3 * j + 0];
        float py = xb[3 * j + 1];
        float pz = xb[3 * j + 2];
        int pos = atomicAdd(&cnt[bin_of(px)], 1);
        pts_s[pos] = make_float4(px, py, pz, -0.5f * (px * px + py * py + pz * pz));
        idx_s[pos] = j;
        rank_of[j] = pos;
    }
    __syncthreads();

    // ---- 4) query phase: query = ORIGINAL index (exactly-once coverage);
    //         result is invariant to the nondeterministic within-bin order.
    const int w = tid >> 5, l = tid & 31;
    if (l < 8) {
        const int q = blockIdx.x * QPB + (w << 3) + l;   // original point index
        if (q < NPTS) {
            const int r = rank_of[q];                    // its sorted position
            const float4 qp = pts_s[r];
            const float qx = qp.x, qy = qp.y, qz = qp.z;
            const float qh2 = -2.0f * qp.w;              // ||q||^2 (exact *2)

            float v0 = -CUDART_INF_F, v1 = -CUDART_INF_F, v2 = -CUDART_INF_F, v3 = -CUDART_INF_F;
            int   o0 = 0, o1 = 0, o2 = 0, o3 = 0;        // original indices (tie-break)
            int   p0 = 0, p1 = 0, p2 = 0, p3 = 0;        // sorted positions (coord fetch)
            float d4sq = CUDART_INF_F;

            #pragma unroll
            for (int dir = 0; dir < 2; ++dir) {
                int pos = dir ? (r - 1) : r;
                const int step = dir ? -1 : 1;
                const int lim = dir ? -1 : NPTS;
                while (pos != lim) {
                    const float4 p = pts_s[pos];
                    const float dx = dir ? (qx - p.x) : (p.x - qx);
                    const float t  = dx - BINW;          // within-bin jitter margin
                    if (t > 0.0f && t * t > d4sq) break; // sound prune for ANY bin order
                    float s = __fmaf_rn(qx, p.x, p.w);
                    s       = __fmaf_rn(qy, p.y, s);
                    s       = __fmaf_rn(qz, p.z, s);
                    if (s >= v3) {
                        const int oj = idx_s[pos];
                        if (better(s, oj, v3, o3)) {
                            if (better(s, oj, v2, o2)) {
                                v3 = v2; o3 = o2; p3 = p2;
                                if (better(s, oj, v1, o1)) {
                                    v2 = v1; o2 = o1; p2 = p1;
                                    if (better(s, oj, v0, o0)) {
                                        v1 = v0; o1 = o0; p1 = p0;
                                        v0 = s; o0 = oj; p0 = pos;
                                    } else { v1 = s; o1 = oj; p1 = pos; }
                                } else { v2 = s; o2 = oj; p2 = pos; }
                            } else { v3 = s; o3 = oj; p3 = pos; }
                            d4sq = qh2 - 2.0f * v3 + SLACK;
                        }
                    }
                    pos += step;
                }
            }

            // ---- 5) gather + write 12 floats as 3x STG.128 at row q
            const float4 a = pts_s[p0];
            const float4 c = pts_s[p1];
            const float4 d = pts_s[p2];
            const float4 e = pts_s[p3];
            float4* __restrict__ o4 = (float4*)(out + ((size_t)b * NPTS + q) * KNN * 3);
            o4[0] = make_float4(a.x, a.y, a.z, c.x);
            o4[1] = make_float4(c.y, c.z, d.x, d.y);
            o4[2] = make_float4(d.z, e.x, e.y, e.z);
        }
    }
}

extern "C" void kernel_launch(void* const* d_in, const int* in_sizes, int n_in,
                              void* d_out, int out_size) {
    (void)n_in; (void)in_sizes; (void)out_size;
    const float* x = (const float*)d_in[0];
    float* out = (float*)d_out;

    cudaFuncSetAttribute(knn_sorted_kernel,
                         cudaFuncAttributeMaxDynamicSharedMemorySize, SMEM_BYTES);

    dim3 grid(GRPX, BATCH, 1);   // 148 blocks = 1 full wave
    dim3 block(THREADS, 1, 1);
    knn_sorted_kernel<<<grid, block, SMEM_BYTES>>>(x, out);
}

// round 11
// speedup vs baseline: 4.5278x; 4.5278x over previous
#include <cuda_runtime.h>
#include <math_constants.h>

#define NPTS   8192
#define BATCH  4
#define KNN    4
#define QPB    224                 // queries per block
#define THREADS 896                // 28 warps; 8 queries per warp, warp-cooperative
#define GRPX   37                  // 37*4 = 148 blocks = 1 full wave
#define QPW    8                   // queries per warp

#define NBINS  512
#define XMIN   (-6.0f)
#define BINW   (12.0f / NBINS)     // within-bin jitter margin
#define INVW   (NBINS / 12.0f)
#define SLACK  1e-3f               // absorbs all fp32 rounding in the prune bound

#define PTS_BYTES (NPTS * 16)
#define IDX_BYTES (NPTS * 4)
#define SMEM_BYTES (PTS_BYTES + 2 * IDX_BYTES + NBINS * 4 * 2)   // 200704 B

#define FULL 0xFFFFFFFFu

__device__ __forceinline__ int bin_of(float px) {
    int bin = (int)__fmul_rn(__fsub_rn(px, XMIN), INVW);
    return min(max(bin, 0), NBINS - 1);
}

__device__ __forceinline__ bool better(float s, int oj, float v, int iv) {
    return (s > v) | ((s == v) & (oj < iv));
}

__global__ __launch_bounds__(THREADS, 1)
void knn_sorted_kernel(const float* __restrict__ x, float* __restrict__ out) {
    extern __shared__ char smem_raw[];
    float4* __restrict__ pts_s   = (float4*)smem_raw;
    int*    __restrict__ idx_s   = (int*)(smem_raw + PTS_BYTES);
    int*    __restrict__ rank_of = (int*)(smem_raw + PTS_BYTES + IDX_BYTES);
    int*    __restrict__ cnt     = (int*)(smem_raw + PTS_BYTES + 2 * IDX_BYTES);
    int*    __restrict__ tmp     = cnt + NBINS;

    const int b = blockIdx.y;
    const float* __restrict__ xb = x + (size_t)b * NPTS * 3;
    const int tid = threadIdx.x;

    // ---- 1) histogram over x-bins
    for (int i = tid; i < NBINS; i += THREADS) cnt[i] = 0;
    __syncthreads();
    for (int j = tid; j < NPTS; j += THREADS)
        atomicAdd(&cnt[bin_of(xb[3 * j])], 1);
    __syncthreads();

    // ---- 2) exclusive prefix (Kogge-Stone)
    if (tid < NBINS) tmp[tid] = cnt[tid];
    __syncthreads();
    for (int d = 1; d < NBINS; d <<= 1) {
        int v = 0;
        if (tid < NBINS && tid >= d) v = tmp[tid - d];
        __syncthreads();
        if (tid < NBINS) tmp[tid] += v;
        __syncthreads();
    }
    if (tid < NBINS) cnt[tid] = tmp[tid] - cnt[tid];
    __syncthreads();

    // ---- 3) scatter into bin-sorted order; record rank of each original index
    for (int j = tid; j < NPTS; j += THREADS) {
        float px = xb[3 * j + 0];
        float py = xb[3 * j + 1];
        float pz = xb[3 * j + 2];
        int pos = atomicAdd(&cnt[bin_of(px)], 1);
        pts_s[pos] = make_float4(px, py, pz, -0.5f * (px * px + py * py + pz * pz));
        idx_s[pos] = j;
        rank_of[j] = pos;
    }
    __syncthreads();

    // ---- 4) warp-cooperative query phase: 32 lanes scan 32 candidates of ONE query.
    const int w = tid >> 5, l = tid & 31;

    for (int qq = 0; qq < QPW; ++qq) {
        const int q = blockIdx.x * QPB + w * QPW + qq;   // original point index
        if (q >= NPTS) break;

        const int r = rank_of[q];                        // broadcast LDS (uniform)
        const float4 qp = pts_s[r];
        const float qx = qp.x, qy = qp.y, qz = qp.z;
        const float qh2 = -2.0f * qp.w;                  // ||q||^2

        // top-4 state replicated in every lane (all lanes update identically)
        float v0 = -CUDART_INF_F, v1 = -CUDART_INF_F, v2 = -CUDART_INF_F, v3 = -CUDART_INF_F;
        int   o0 = 0, o1 = 0, o2 = 0, o3 = 0;
        int   p0 = 0, p1 = 0, p2 = 0, p3 = 0;
        float d4sq = CUDART_INF_F;

        #pragma unroll
        for (int dir = 0; dir < 2; ++dir) {
            int start = dir ? (r - 1 - l) : (r + l);     // per-lane position
            const int step = dir ? -32 : 32;

            for (;;) {
                const int pos = start;
                const bool valid = dir ? (pos >= 0) : (pos < NPTS);

                float s = -CUDART_INF_F;
                bool beyond = !valid;
                if (valid) {
                    const float4 p = pts_s[pos];          // coalesced LDS.128
                    const float dx = dir ? (qx - p.x) : (p.x - qx);
                    const float t  = dx - BINW;
                    beyond = (t > 0.0f) && (t * t > d4sq);  // chunk-start d4sq: conservative
                    s = __fmaf_rn(qx, p.x, p.w);
                    s = __fmaf_rn(qy, p.y, s);
                    s = __fmaf_rn(qz, p.z, s);
                }

                const unsigned stop_mask = __ballot_sync(FULL, beyond);
                unsigned cand = __ballot_sync(FULL, valid && (s >= v3));

                // Serialize rare winners; every lane applies the same insert.
                while (cand) {
                    const int src = __ffs(cand) - 1;
                    cand &= cand - 1;
                    const float cs  = __shfl_sync(FULL, s, src);
                    const int   cps = __shfl_sync(FULL, pos, src);
                    const int   coj = idx_s[cps];         // uniform addr -> broadcast
                    if (better(cs, coj, v3, o3)) {
                        if (better(cs, coj, v2, o2)) {
                            v3 = v2; o3 = o2; p3 = p2;
                            if (better(cs, coj, v1, o1)) {
                                v2 = v1; o2 = o1; p2 = p1;
                                if (better(cs, coj, v0, o0)) {
                                    v1 = v0; o1 = o0; p1 = p0;
                                    v0 = cs; o0 = coj; p0 = cps;
                                } else { v1 = cs; o1 = coj; p1 = cps; }
                            } else { v2 = cs; o2 = coj; p2 = cps; }
                        } else { v3 = cs; o3 = coj; p3 = cps; }
                        d4sq = qh2 - 2.0f * v3 + SLACK;
                    }
                }

                if (stop_mask) break;   // some lane passed the sound prune bound -> done
                start += step;
            }
        }

        // ---- 5) write: lanes 0..3 each emit one neighbor's 3 floats (row q)
        if (l < KNN) {
            const int ps = (l == 0) ? p0 : (l == 1) ? p1 : (l == 2) ? p2 : p3;
            const float4 nb = pts_s[ps];
            float* __restrict__ o = out + (((size_t)b * NPTS + q) * KNN + l) * 3;
            o[0] = nb.x; o[1] = nb.y; o[2] = nb.z;
        }
    }
}

extern "C" void kernel_launch(void* const* d_in, const int* in_sizes, int n_in,
                              void* d_out, int out_size) {
    (void)n_in; (void)in_sizes; (void)out_size;
    const float* x = (const float*)d_in[0];
    float* out = (float*)d_out;

    cudaFuncSetAttribute(knn_sorted_kernel,
                         cudaFuncAttributeMaxDynamicSharedMemorySize, SMEM_BYTES);

    dim3 grid(GRPX, BATCH, 1);   // 148 blocks = 1 full wave
    dim3 block(THREADS, 1, 1);
    knn_sorted_kernel<<<grid, block, SMEM_BYTES>>>(x, out);
}

// round 12
// speedup vs baseline: 5.0361x; 1.1123x over previous
#include <cuda_runtime.h>
#include <math_constants.h>

#define NPTS   8192
#define BATCH  4
#define KNN    4
#define QPB    224
#define THREADS 896                // 28 warps; warp-cooperative, 8 queries/warp
#define GRPX   37                  // 37*4 = 148 blocks = 1 full wave
#define QPW    8

#define NBINS  512
#define XMIN   (-6.0f)
#define BINW   (12.0f / NBINS)
#define INVW   (NBINS / 12.0f)
#define SLACK  1e-3f               // >> all fp32 rounding at these magnitudes
#define GUARD  32                  // sentinel entries each side of pts_s

#define PTS_BYTES ((NPTS + 2 * GUARD) * 16)
#define IDX_BYTES (NPTS * 4)
#define SMEM_BYTES (PTS_BYTES + 2 * IDX_BYTES + NBINS * 4 * 2)   // 202752 B

#define FULL 0xFFFFFFFFu

__device__ __forceinline__ int bin_of(float px) {
    int bin = (int)__fmul_rn(__fsub_rn(px, XMIN), INVW);
    return min(max(bin, 0), NBINS - 1);
}

__device__ __forceinline__ bool better(float s, int oj, float v, int iv) {
    return (s > v) | ((s == v) & (oj < iv));
}

__global__ __launch_bounds__(THREADS, 1)
void knn_sorted_kernel(const float* __restrict__ x, float* __restrict__ out) {
    extern __shared__ char smem_raw[];
    float4* __restrict__ pts_s   = (float4*)smem_raw + GUARD;   // logical [ -GUARD, NPTS+GUARD )
    int*    __restrict__ idx_s   = (int*)(smem_raw + PTS_BYTES);
    int*    __restrict__ rank_of = (int*)(smem_raw + PTS_BYTES + IDX_BYTES);
    int*    __restrict__ cnt     = (int*)(smem_raw + PTS_BYTES + 2 * IDX_BYTES);
    int*    __restrict__ tmp     = cnt + NBINS;

    const int b = blockIdx.y;
    const float* __restrict__ xb = x + (size_t)b * NPTS * 3;
    const int tid = threadIdx.x;

    // ---- 0) sentinel guards: beyond==true, s==-inf/NaN -> never a candidate
    if (tid < 2 * GUARD) {
        const int pos = (tid < GUARD) ? (tid - GUARD) : (NPTS + tid - GUARD);
        const float gx = (tid < GUARD) ? -1e30f : 1e30f;
        pts_s[pos] = make_float4(gx, 0.0f, 0.0f, -CUDART_INF_F);
    }

    // ---- 1) histogram over x-bins
    for (int i = tid; i < NBINS; i += THREADS) cnt[i] = 0;
    __syncthreads();
    for (int j = tid; j < NPTS; j += THREADS)
        atomicAdd(&cnt[bin_of(xb[3 * j])], 1);
    __syncthreads();

    // ---- 2) exclusive prefix (Kogge-Stone)
    if (tid < NBINS) tmp[tid] = cnt[tid];
    __syncthreads();
    for (int d = 1; d < NBINS; d <<= 1) {
        int v = 0;
        if (tid < NBINS && tid >= d) v = tmp[tid - d];
        __syncthreads();
        if (tid < NBINS) tmp[tid] += v;
        __syncthreads();
    }
    if (tid < NBINS) cnt[tid] = tmp[tid] - cnt[tid];
    __syncthreads();

    // ---- 3) scatter into bin-sorted order; record each original index's rank
    for (int j = tid; j < NPTS; j += THREADS) {
        float px = xb[3 * j + 0];
        float py = xb[3 * j + 1];
        float pz = xb[3 * j + 2];
        int pos = atomicAdd(&cnt[bin_of(px)], 1);
        pts_s[pos] = make_float4(px, py, pz, -0.5f * (px * px + py * py + pz * pz));
        idx_s[pos] = j;
        rank_of[j] = pos;
    }
    __syncthreads();

    // ---- 4) warp-cooperative queries
    const int w = tid >> 5, l = tid & 31;

    for (int qq = 0; qq < QPW; ++qq) {
        const int q = blockIdx.x * QPB + w * QPW + qq;   // warp-uniform
        if (q >= NPTS) break;

        const int r = rank_of[q];
        const float4 qp = pts_s[r];
        const float qx = qp.x, qy = qp.y, qz = qp.z;
        const float qh2 = -2.0f * qp.w;                  // ||q||^2

        float v0 = -CUDART_INF_F, v1 = -CUDART_INF_F, v2 = -CUDART_INF_F, v3 = -CUDART_INF_F;
        int   o0 = 0, o1 = 0, o2 = 0, o3 = 0;
        int   p0 = 0, p1 = 0, p2 = 0, p3 = 0;
        float d4sq, xlim;

        // ---- 4a) seed: exactly insert ranks [lo, hi] (5..9 cands -> top4 full)
        const int lo = max(0, r - 4);
        const int hi = min(NPTS - 1, r + 4);
        {
            const int pos = lo + l;
            float s = -CUDART_INF_F;
            if (pos <= hi) {
                const float4 p = pts_s[pos];
                s = __fmaf_rn(qx, p.x, p.w);
                s = __fmaf_rn(qy, p.y, s);
                s = __fmaf_rn(qz, p.z, s);
            }
            unsigned cand = __ballot_sync(FULL, pos <= hi);
            while (cand) {
                const int src = __ffs(cand) - 1;
                cand &= cand - 1;
                const float cs  = __shfl_sync(FULL, s, src);
                const int   cps = __shfl_sync(FULL, pos, src);
                const int   coj = idx_s[cps];
                if (better(cs, coj, v3, o3)) {
                    if (better(cs, coj, v2, o2)) {
                        v3 = v2; o3 = o2; p3 = p2;
                        if (better(cs, coj, v1, o1)) {
                            v2 = v1; o2 = o1; p2 = p1;
                            if (better(cs, coj, v0, o0)) {
                                v1 = v0; o1 = o0; p1 = p0;
                                v0 = cs; o0 = coj; p0 = cps;
                            } else { v1 = cs; o1 = coj; p1 = cps; }
                        } else { v2 = cs; o2 = coj; p2 = cps; }
                    } else { v3 = cs; o3 = coj; p3 = cps; }
                }
            }
            d4sq = qh2 - 2.0f * v3 + SLACK;              // v3 finite (>=5 seeds)
            xlim = __fadd_ru(BINW, __fsqrt_ru(d4sq));
        }

        // ---- 4b) main chunked walk, both directions, outside the seed window
        #pragma unroll
        for (int dir = 0; dir < 2; ++dir) {
            int pos = dir ? (lo - 1 - l) : (hi + 1 + l);
            const int step = dir ? -32 : 32;

            for (;;) {
                const float4 p = pts_s[pos];             // guards make this always safe
                const float dx = dir ? (qx - p.x) : (p.x - qx);
                const bool beyond = dx > xlim;           // 1 FSETP sound prune
                float s = __fmaf_rn(qx, p.x, p.w);
                s = __fmaf_rn(qy, p.y, s);
                s = __fmaf_rn(qz, p.z, s);
                const bool candp = (s >= v3);            // guards: -inf/NaN -> false

                const unsigned bm = __ballot_sync(FULL, beyond | candp);
                if (bm) {                                // rare after seeding
                    const unsigned stopm = __ballot_sync(FULL, beyond);
                    unsigned cand = bm & ~stopm;
                    while (cand) {
                        const int src = __ffs(cand) - 1;
                        cand &= cand - 1;
                        const float cs  = __shfl_sync(FULL, s, src);
                        const int   cps = __shfl_sync(FULL, pos, src);
                        const int   coj = idx_s[cps];
                        if (better(cs, coj, v3, o3)) {
                            if (better(cs, coj, v2, o2)) {
                                v3 = v2; o3 = o2; p3 = p2;
                                if (better(cs, coj, v1, o1)) {
                                    v2 = v1; o2 = o1; p2 = p1;
                                    if (better(cs, coj, v0, o0)) {
                                        v1 = v0; o1 = o0; p1 = p0;
                                        v0 = cs; o0 = coj; p0 = cps;
                                    } else { v1 = cs; o1 = coj; p1 = cps; }
                                } else { v2 = cs; o2 = coj; p2 = cps; }
                            } else { v3 = cs; o3 = coj; p3 = cps; }
                            d4sq = qh2 - 2.0f * v3 + SLACK;
                            xlim = __fadd_ru(BINW, __fsqrt_ru(d4sq));
                        }
                    }
                    if (stopm) break;
                }
                pos += step;
            }
        }

        // ---- 5) lanes 0..3 write one neighbor each (row = original index q)
        if (l < KNN) {
            const int ps = (l == 0) ? p0 : (l == 1) ? p1 : (l == 2) ? p2 : p3;
            const float4 nb = pts_s[ps];
            float* __restrict__ o = out + (((size_t)b * NPTS + q) * KNN + l) * 3;
            o[0] = nb.x; o[1] = nb.y; o[2] = nb.z;
        }
    }
}

extern "C" void kernel_launch(void* const* d_in, const int* in_sizes, int n_in,
                              void* d_out, int out_size) {
    (void)n_in; (void)in_sizes; (void)out_size;
    const float* x = (const float*)d_in[0];
    float* out = (float*)d_out;

    cudaFuncSetAttribute(knn_sorted_kernel,
                         cudaFuncAttributeMaxDynamicSharedMemorySize, SMEM_BYTES);

    dim3 grid(GRPX, BATCH, 1);   // 148 blocks = 1 full wave
    dim3 block(THREADS, 1, 1);
    knn_sorted_kernel<<<grid, block, SMEM_BYTES>>>(x, out);
}